// round 5
// baseline (speedup 1.0000x reference)
#include <cuda_runtime.h>
#include <math.h>

#define BDIM 4
#define CDIM 256
#define NDIM 4096

#define QT 128      // queries per CTA
#define KT 64       // keys per tile
#define CCH 32      // channel chunk for K staging

typedef unsigned long long u64;

// Scratch for projected Q (B,N,C), K (B,C,N), V (B,C,N)
__device__ float g_Q[BDIM * NDIM * CDIM];
__device__ float g_K[BDIM * CDIM * NDIM];
__device__ float g_V[BDIM * CDIM * NDIM];

// ---- packed f32x2 helpers (sm_103a FFMA2 path, PTX-only) -------------------
__device__ __forceinline__ u64 pack2(float lo, float hi) {
    u64 r; asm("mov.b64 %0, {%1, %2};" : "=l"(r) : "f"(lo), "f"(hi)); return r;
}
__device__ __forceinline__ void unpack2(u64 v, float& lo, float& hi) {
    asm("mov.b64 {%0, %1}, %2;" : "=f"(lo), "=f"(hi) : "l"(v));
}
__device__ __forceinline__ u64 fma2(u64 a, u64 b, u64 c) {
    u64 d; asm("fma.rn.f32x2 %0, %1, %2, %3;" : "=l"(d) : "l"(a), "l"(b), "l"(c));
    return d;
}
__device__ __forceinline__ u64 mul2(u64 a, u64 b) {
    u64 d; asm("mul.rn.f32x2 %0, %1, %2;" : "=l"(d) : "l"(a), "l"(b)); return d;
}

// ---------------------------------------------------------------------------
// Projection kernel: out = W(256x256) @ X(256x4096) + bias per batch, for
// Wq/Wk/Wv. Q stored (B,N,C); K,V stored (B,C,N).
// ---------------------------------------------------------------------------
__global__ __launch_bounds__(256) void proj_kernel(
    const float* __restrict__ x,
    const float* __restrict__ Wq, const float* __restrict__ bq,
    const float* __restrict__ Wk, const float* __restrict__ bk,
    const float* __restrict__ Wv, const float* __restrict__ bv)
{
    __shared__ float w_s[16][68];
    __shared__ float x_s[16][64];

    const int n0 = blockIdx.x * 64;
    const int o0 = blockIdx.y * 64;
    const int b     = blockIdx.z / 3;
    const int which = blockIdx.z % 3;
    const float* W    = (which == 0) ? Wq : (which == 1) ? Wk : Wv;
    const float* bias = (which == 0) ? bq : (which == 1) ? bk : bv;

    const int t  = threadIdx.x;
    const int tx = t & 15;
    const int ty = t >> 4;

    const float* xb = x + (size_t)b * CDIM * NDIM;

    float acc[4][4];
    #pragma unroll
    for (int i = 0; i < 4; i++)
        #pragma unroll
        for (int j = 0; j < 4; j++) acc[i][j] = 0.f;

    const int lo = t >> 2;
    const int lc = (t & 3) << 2;
    const int xr = t >> 4;
    const int xn = (t & 15) << 2;

    for (int c0 = 0; c0 < CDIM; c0 += 16) {
        float4 wv4 = *(const float4*)&W[(size_t)(o0 + lo) * CDIM + c0 + lc];
        float4 xv4 = *(const float4*)&xb[(size_t)(c0 + xr) * NDIM + n0 + xn];
        __syncthreads();
        w_s[lc + 0][lo] = wv4.x;
        w_s[lc + 1][lo] = wv4.y;
        w_s[lc + 2][lo] = wv4.z;
        w_s[lc + 3][lo] = wv4.w;
        *(float4*)&x_s[xr][xn] = xv4;
        __syncthreads();
        #pragma unroll
        for (int kk = 0; kk < 16; kk++) {
            float4 a4 = *(const float4*)&w_s[kk][ty << 2];
            float4 b4 = *(const float4*)&x_s[kk][tx << 2];
            float a[4] = {a4.x, a4.y, a4.z, a4.w};
            float bb[4] = {b4.x, b4.y, b4.z, b4.w};
            #pragma unroll
            for (int i = 0; i < 4; i++)
                #pragma unroll
                for (int j = 0; j < 4; j++)
                    acc[i][j] = fmaf(a[i], bb[j], acc[i][j]);
        }
    }

    float bo[4];
    #pragma unroll
    for (int i = 0; i < 4; i++) bo[i] = bias[o0 + (ty << 2) + i];

    if (which == 0) {
        #pragma unroll
        for (int i = 0; i < 4; i++)
            #pragma unroll
            for (int j = 0; j < 4; j++) {
                int n = n0 + (tx << 2) + j;
                int o = o0 + (ty << 2) + i;
                g_Q[((size_t)b * NDIM + n) * CDIM + o] = acc[i][j] + bo[i];
            }
    } else {
        float* dst = (which == 1) ? g_K : g_V;
        #pragma unroll
        for (int i = 0; i < 4; i++)
            #pragma unroll
            for (int j = 0; j < 4; j++) {
                int n = n0 + (tx << 2) + j;
                int o = o0 + (ty << 2) + i;
                dst[((size_t)b * CDIM + o) * NDIM + n] = acc[i][j] + bo[i];
            }
    }
}

// ---------------------------------------------------------------------------
// Fused flash-attention v2.1 (v2 + fixed epilogue store covering all 256 ch).
//   CTA = 128 query rows. Q tile persistent in SMEM (loaded once).
//   Per 64-key tile: S(128x64) via FFMA2, online softmax, O update in two
//   128-channel halves. Thread map 16x16: S: 8q x 4k; O: 8q x 16ch.
// SMEM (floats):
//   q_s [256][132] = 33792     (persistent Q, [c][q]; reused as O staging)
//   k_s [32][64]   = 2048
//   p_s [128][68]  = 8704      ([q][m])
//   v_s [64][132]  = 8448      ([m][c_local], one 128-ch half at a time)
// ---------------------------------------------------------------------------
#define QS_F (256 * 132)
#define KS_F (32 * 64)
#define PS_F (128 * 68)
#define VS_F (64 * 132)
#define ATTN_SMEM_F (QS_F + KS_F + PS_F + VS_F)
#define ATTN_SMEM_BYTES (ATTN_SMEM_F * 4)   // 211968 B

__global__ __launch_bounds__(256, 1) void attn_kernel(float* __restrict__ out)
{
    extern __shared__ float sm[];
    float* q_s = sm;
    float* k_s = sm + QS_F;
    float* p_s = k_s + KS_F;
    float* v_s = p_s + PS_F;

    const int b  = blockIdx.y;
    const int n0 = blockIdx.x * QT;
    const int t  = threadIdx.x;
    const int tx = t & 15;
    const int ty = t >> 4;

    const float* Kb0 = g_K + (size_t)b * CDIM * NDIM;
    const float* Vb0 = g_V + (size_t)b * CDIM * NDIM;

    // ---- load Q tile once: g_Q is (N,C) row-major -> q_s[c][q] ------------
    {
        const int r  = t >> 1;            // query row 0..127
        const int cb = (t & 1) * 128;     // channel half
        const float* src = g_Q + ((size_t)b * NDIM + n0 + r) * CDIM + cb;
        #pragma unroll
        for (int i = 0; i < 128; i += 4) {
            float4 v = *(const float4*)(src + i);
            q_s[(cb + i + 0) * 132 + r] = v.x;
            q_s[(cb + i + 1) * 132 + r] = v.y;
            q_s[(cb + i + 2) * 132 + r] = v.z;
            q_s[(cb + i + 3) * 132 + r] = v.w;
        }
    }

    u64 O[8][8];                         // [query][ch-pair]; pairs 0-3 half0, 4-7 half1
    #pragma unroll
    for (int i = 0; i < 8; i++)
        #pragma unroll
        for (int j = 0; j < 8; j++) O[i][j] = 0ull;

    float mrow[8], lrow[8];
    #pragma unroll
    for (int i = 0; i < 8; i++) { mrow[i] = -INFINITY; lrow[i] = 0.f; }

    for (int m0 = 0; m0 < NDIM; m0 += KT) {
        u64 Sp[4][4];                    // [q-pair][key]
        #pragma unroll
        for (int i = 0; i < 4; i++)
            #pragma unroll
            for (int j = 0; j < 4; j++) Sp[i][j] = 0ull;

        // ---- S = Q @ K ----------------------------------------------------
        for (int c0 = 0; c0 < CDIM; c0 += CCH) {
            const float* kp = Kb0 + (size_t)(c0 + (t >> 3)) * NDIM + m0 + (t & 7) * 8;
            float4 ka = ((const float4*)kp)[0];
            float4 kb = ((const float4*)kp)[1];
            __syncthreads();
            *(float4*)&k_s[(t >> 3) * 64 + (t & 7) * 8]     = ka;
            *(float4*)&k_s[(t >> 3) * 64 + (t & 7) * 8 + 4] = kb;
            __syncthreads();
            #pragma unroll 8
            for (int kk = 0; kk < CCH; kk++) {
                float4 qa = *(const float4*)&q_s[(c0 + kk) * 132 + ty * 8];
                float4 qb = *(const float4*)&q_s[(c0 + kk) * 132 + ty * 8 + 4];
                float4 kv = *(const float4*)&k_s[kk * 64 + tx * 4];
                u64 qp[4] = { pack2(qa.x, qa.y), pack2(qa.z, qa.w),
                              pack2(qb.x, qb.y), pack2(qb.z, qb.w) };
                u64 kd[4] = { pack2(kv.x, kv.x), pack2(kv.y, kv.y),
                              pack2(kv.z, kv.z), pack2(kv.w, kv.w) };
                #pragma unroll
                for (int i = 0; i < 4; i++)
                    #pragma unroll
                    for (int j = 0; j < 4; j++)
                        Sp[i][j] = fma2(qp[i], kd[j], Sp[i][j]);
            }
        }

        // ---- online softmax ----------------------------------------------
        float s[8][4];
        #pragma unroll
        for (int i = 0; i < 4; i++)
            #pragma unroll
            for (int j = 0; j < 4; j++)
                unpack2(Sp[i][j], s[2 * i][j], s[2 * i + 1][j]);

        #pragma unroll
        for (int i = 0; i < 8; i++) {
            float rmax = fmaxf(fmaxf(s[i][0], s[i][1]), fmaxf(s[i][2], s[i][3]));
            #pragma unroll
            for (int sh = 8; sh > 0; sh >>= 1)
                rmax = fmaxf(rmax, __shfl_xor_sync(0xffffffffu, rmax, sh));
            float mnew = fmaxf(mrow[i], rmax);
            float corr = __expf(mrow[i] - mnew);
            float rsum = 0.f;
            #pragma unroll
            for (int j = 0; j < 4; j++) {
                s[i][j] = __expf(s[i][j] - mnew);
                rsum += s[i][j];
            }
            #pragma unroll
            for (int sh = 8; sh > 0; sh >>= 1)
                rsum += __shfl_xor_sync(0xffffffffu, rsum, sh);
            lrow[i] = lrow[i] * corr + rsum;
            mrow[i] = mnew;
            u64 c2 = pack2(corr, corr);
            #pragma unroll
            for (int cp = 0; cp < 8; cp++) O[i][cp] = mul2(O[i][cp], c2);
        }

        // ---- stage P ([q][m]) --------------------------------------------
        #pragma unroll
        for (int i = 0; i < 8; i++)
            #pragma unroll
            for (int j = 0; j < 4; j++)
                p_s[(ty * 8 + i) * 68 + tx * 4 + j] = s[i][j];

        // ---- O += P @ V^T, two 128-channel halves ------------------------
        #pragma unroll
        for (int half = 0; half < 2; half++) {
            const float* vp = Vb0 + (size_t)(half * 128 + (t >> 1)) * NDIM
                              + m0 + (t & 1) * 32;
            float4 va[8];
            #pragma unroll
            for (int u = 0; u < 8; u++) va[u] = ((const float4*)vp)[u];
            __syncthreads();            // prior readers of v_s done; p_s visible
            {
                const int c  = t >> 1;
                const int mb = (t & 1) * 32;
                #pragma unroll
                for (int u = 0; u < 8; u++) {
                    v_s[(mb + 4 * u + 0) * 132 + c] = va[u].x;
                    v_s[(mb + 4 * u + 1) * 132 + c] = va[u].y;
                    v_s[(mb + 4 * u + 2) * 132 + c] = va[u].z;
                    v_s[(mb + 4 * u + 3) * 132 + c] = va[u].w;
                }
            }
            __syncthreads();

            const int cb = half * 4;
            #pragma unroll 2
            for (int m = 0; m < KT; m++) {
                u64 pd[8];
                #pragma unroll
                for (int i = 0; i < 8; i++) {
                    float pv = p_s[(ty * 8 + i) * 68 + m];
                    pd[i] = pack2(pv, pv);
                }
                float4 v0 = *(const float4*)&v_s[m * 132 + tx * 8];
                float4 v1 = *(const float4*)&v_s[m * 132 + tx * 8 + 4];
                u64 vpk[4] = { pack2(v0.x, v0.y), pack2(v0.z, v0.w),
                               pack2(v1.x, v1.y), pack2(v1.z, v1.w) };
                #pragma unroll
                for (int i = 0; i < 8; i++)
                    #pragma unroll
                    for (int j = 0; j < 4; j++)
                        O[i][cb + j] = fma2(pd[i], vpk[j], O[i][cb + j]);
            }
            __syncthreads();            // done reading v_s before next half restages
        }
    }

    // ---- epilogue: normalize, transpose via q_s, coalesced store ----------
    __syncthreads();                    // q_s free for reuse
    #pragma unroll
    for (int i = 0; i < 8; i++) {
        float inv = 1.f / lrow[i];
        u64 inv2 = pack2(inv, inv);
        int r = ty * 8 + i;
        #pragma unroll
        for (int cp = 0; cp < 8; cp++) {
            u64 sc = mul2(O[i][cp], inv2);
            float lo, hi;
            unpack2(sc, lo, hi);
            int ch = (cp < 4) ? (tx * 8 + 2 * cp) : (128 + tx * 8 + 2 * (cp - 4));
            q_s[(ch + 0) * 132 + r] = lo;
            q_s[(ch + 1) * 132 + r] = hi;
        }
    }
    __syncthreads();
    {
        // FIXED: one thread per channel (t = 0..255), store the full
        // 128-query row for that channel. Coalesced: row is contiguous.
        float* dst = out + ((size_t)b * CDIM + t) * NDIM + n0;
        const float* src = &q_s[t * 132];
        #pragma unroll
        for (int i = 0; i < 128; i += 4)
            *(float4*)(dst + i) = *(const float4*)(src + i);
    }
}

// ---------------------------------------------------------------------------
extern "C" void kernel_launch(void* const* d_in, const int* in_sizes, int n_in,
                              void* d_out, int out_size)
{
    const float* x  = (const float*)d_in[0];
    const float* Wq = (const float*)d_in[1];
    const float* bq = (const float*)d_in[2];
    const float* Wk = (const float*)d_in[3];
    const float* bk = (const float*)d_in[4];
    const float* Wv = (const float*)d_in[5];
    const float* bv = (const float*)d_in[6];
    float* out = (float*)d_out;

    cudaFuncSetAttribute(attn_kernel,
                         cudaFuncAttributeMaxDynamicSharedMemorySize,
                         ATTN_SMEM_BYTES);

    dim3 pg(NDIM / 64, CDIM / 64, BDIM * 3);
    proj_kernel<<<pg, 256>>>(x, Wq, bq, Wk, bk, Wv, bv);

    dim3 ag(NDIM / QT, BDIM);
    attn_kernel<<<ag, 256, ATTN_SMEM_BYTES>>>(out);
}

// round 9
// speedup vs baseline: 1.3712x; 1.3712x over previous
#include <cuda_runtime.h>
#include <cuda_bf16.h>
#include <math.h>
#include <stdint.h>

#define BDIM 4
#define CDIM 256
#define NDIM 4096

// ---------------- global scratch (static device allocations) ---------------
__device__ __nv_bfloat16 g_Qh[(size_t)BDIM * NDIM * CDIM];  // (B,N,C)
__device__ __nv_bfloat16 g_Ql[(size_t)BDIM * NDIM * CDIM];
__device__ __nv_bfloat16 g_Kh[(size_t)BDIM * NDIM * CDIM];  // (B,N,C)
__device__ __nv_bfloat16 g_Kl[(size_t)BDIM * NDIM * CDIM];
__device__ __nv_bfloat16 g_Vh[(size_t)BDIM * CDIM * NDIM];  // (B,C,N)
__device__ __nv_bfloat16 g_Vl[(size_t)BDIM * CDIM * NDIM];
__device__ float         g_S [(size_t)BDIM * NDIM * NDIM];  // (B,N,N) energy
__device__ __nv_bfloat16 g_Ph[(size_t)BDIM * NDIM * NDIM];  // (B,N,N) attn hi
__device__ __nv_bfloat16 g_Pl[(size_t)BDIM * NDIM * NDIM];  // (B,N,N) attn lo

// ---------------- PTX helpers (baseline sm_80+ features only) ---------------
__device__ __forceinline__ uint32_t smem_u32(const void* p) {
    uint32_t a;
    asm("{ .reg .u64 t; cvta.to.shared.u64 t, %1; cvt.u32.u64 %0, t; }"
        : "=r"(a) : "l"(p));
    return a;
}
__device__ __forceinline__ void ldsm4(uint32_t* r, uint32_t addr) {
    asm volatile("ldmatrix.sync.aligned.m8n8.x4.shared.b16 {%0,%1,%2,%3}, [%4];"
                 : "=r"(r[0]), "=r"(r[1]), "=r"(r[2]), "=r"(r[3]) : "r"(addr));
}
__device__ __forceinline__ void mma_bf16(float* d, const uint32_t* a,
                                         const uint32_t* b) {
    asm volatile(
        "mma.sync.aligned.m16n8k16.row.col.f32.bf16.bf16.f32 "
        "{%0,%1,%2,%3}, {%4,%5,%6,%7}, {%8,%9}, {%0,%1,%2,%3};"
        : "+f"(d[0]), "+f"(d[1]), "+f"(d[2]), "+f"(d[3])
        : "r"(a[0]), "r"(a[1]), "r"(a[2]), "r"(a[3]), "r"(b[0]), "r"(b[1]));
}

// ---------------------------------------------------------------------------
// Split-bf16 warp-MMA GEMM core.
//   D(128x64 fp32) = sum_k A[128,K] * B[64,K]^T,  A,B as bf16 (hi,lo) pairs,
//   D += Ah*Bh + Ah*Bl + Al*Bh  (Al*Bl dropped, ~2^-18 error).
// K consumed in chunks of 32. Single SMEM buffer, 80B-padded rows
// (conflict-free ldmatrix at 80B stride). Next chunk prefetched to registers
// during compute. 8 warps in 4(m) x 2(n); warp tile 32x32; acc 32 regs.
// SMEM rows: [0,128) Ah, [128,256) Al, [256,320) Bh, [320,384) Bl.
// ---------------------------------------------------------------------------
#define SROW 80

__device__ __forceinline__ void gemm_core(
    const __nv_bfloat16* __restrict__ Ah, const __nv_bfloat16* __restrict__ Al,
    const __nv_bfloat16* __restrict__ Bh, const __nv_bfloat16* __restrict__ Bl,
    int kstride, int nchunks, float* __restrict__ dst)
{
    __shared__ __align__(16) char smem[384 * SROW];
    const uint32_t sb = smem_u32(smem);
    const int tid  = threadIdx.x;
    const int lane = tid & 31;
    const int wid  = tid >> 5;
    const int m0   = (wid & 3) * 32;
    const int n0   = (wid >> 2) * 32;

    // ---- staging map: 6 x 16B units per thread ----------------------------
    const __nv_bfloat16* p[6];
    uint32_t doff[6];
    #pragma unroll
    for (int i = 0; i < 6; i++) {
        int u = i * 256 + tid;
        int row = u >> 2, c16 = u & 3;
        const __nv_bfloat16* base;
        int r;
        if (row < 128)      { base = Ah; r = row; }
        else if (row < 256) { base = Al; r = row - 128; }
        else if (row < 320) { base = Bh; r = row - 256; }
        else                { base = Bl; r = row - 320; }
        p[i]    = base + (size_t)r * kstride + c16 * 8;
        doff[i] = (uint32_t)row * SROW + c16 * 16;
    }

    // ---- ldmatrix lane addressing -----------------------------------------
    const int g = lane >> 3, r8 = lane & 7;
    const int rowA = (g & 1) * 8 + r8, kkA = (g >> 1) * 8;  // a0,a1,a2,a3 order
    const int rowB = (g >> 1) * 8 + r8, kkB = (g & 1) * 8;  // b0t0,b1t0,b0t1,b1t1
    uint32_t aAh[2], aAl[2], aBh[2], aBl[2];
    #pragma unroll
    for (int mt = 0; mt < 2; mt++) {
        aAh[mt] = sb + (uint32_t)(0   + m0 + mt * 16 + rowA) * SROW + kkA * 2;
        aAl[mt] = sb + (uint32_t)(128 + m0 + mt * 16 + rowA) * SROW + kkA * 2;
    }
    #pragma unroll
    for (int np = 0; np < 2; np++) {
        aBh[np] = sb + (uint32_t)(256 + n0 + np * 16 + rowB) * SROW + kkB * 2;
        aBl[np] = sb + (uint32_t)(320 + n0 + np * 16 + rowB) * SROW + kkB * 2;
    }

    float acc[2][4][4];
    #pragma unroll
    for (int mt = 0; mt < 2; mt++)
        #pragma unroll
        for (int nt = 0; nt < 4; nt++)
            #pragma unroll
            for (int e = 0; e < 4; e++) acc[mt][nt][e] = 0.f;

    uint4 pre[6];
    #pragma unroll
    for (int i = 0; i < 6; i++) { pre[i] = *(const uint4*)p[i]; p[i] += 32; }

    for (int ci = 0; ci < nchunks; ci++) {
        __syncthreads();                    // previous compute done
        #pragma unroll
        for (int i = 0; i < 6; i++) *(uint4*)(smem + doff[i]) = pre[i];
        __syncthreads();
        if (ci + 1 < nchunks) {
            #pragma unroll
            for (int i = 0; i < 6; i++) { pre[i] = *(const uint4*)p[i]; p[i] += 32; }
        }
        #pragma unroll
        for (int k16 = 0; k16 < 2; k16++) {
            const uint32_t kb = k16 * 32;   // 16 bf16 = 32 bytes
            uint32_t ah[2][4], al[2][4], bh[2][4], bl[2][4];
            #pragma unroll
            for (int mt = 0; mt < 2; mt++) {
                ldsm4(ah[mt], aAh[mt] + kb);
                ldsm4(al[mt], aAl[mt] + kb);
            }
            #pragma unroll
            for (int np = 0; np < 2; np++) {
                ldsm4(bh[np], aBh[np] + kb);
                ldsm4(bl[np], aBl[np] + kb);
            }
            #pragma unroll
            for (int mt = 0; mt < 2; mt++)
                #pragma unroll
                for (int nt = 0; nt < 4; nt++) {
                    const uint32_t* bfh = &bh[nt >> 1][(nt & 1) * 2];
                    const uint32_t* bfl = &bl[nt >> 1][(nt & 1) * 2];
                    mma_bf16(acc[mt][nt], ah[mt], bfh);
                    mma_bf16(acc[mt][nt], ah[mt], bfl);
                    mma_bf16(acc[mt][nt], al[mt], bfh);
                }
        }
    }

    // ---- epilogue: fragment layout row = lane>>2 (+8), col = 2*(lane&3) ---
    const int er = lane >> 2, ec = (lane & 3) * 2;
    #pragma unroll
    for (int mt = 0; mt < 2; mt++)
        #pragma unroll
        for (int nt = 0; nt < 4; nt++) {
            const int rr = m0 + mt * 16 + er;
            const int cc = n0 + nt * 8 + ec;
            *(float2*)&dst[(size_t)rr * NDIM + cc] =
                make_float2(acc[mt][nt][0], acc[mt][nt][1]);
            *(float2*)&dst[(size_t)(rr + 8) * NDIM + cc] =
                make_float2(acc[mt][nt][2], acc[mt][nt][3]);
        }
}

// ---------------------------------------------------------------------------
// QK: S[b, n, m] = sum_c q[b,n,c] * k[b,m,c].  A=Q rows n, B=K rows m.
// ---------------------------------------------------------------------------
__global__ __launch_bounds__(256, 2) void qk_kernel()
{
    const int mt = blockIdx.x;   // key tile (64 wide)
    const int nt = blockIdx.y;   // query tile (128 tall)
    const int b  = blockIdx.z;
    const size_t ao = ((size_t)b * NDIM + (size_t)nt * 128) * CDIM;
    const size_t bo = ((size_t)b * NDIM + (size_t)mt * 64) * CDIM;
    float* dst = g_S + ((size_t)b * NDIM + (size_t)nt * 128) * NDIM + mt * 64;
    gemm_core(g_Qh + ao, g_Ql + ao, g_Kh + bo, g_Kl + bo, CDIM, CDIM / 32, dst);
}

// ---------------------------------------------------------------------------
// PV: out[b, c, n] = sum_m v[b,c,m] * P[b,n,m].  A=V rows c, B=P rows n.
// ---------------------------------------------------------------------------
__global__ __launch_bounds__(256, 2) void pv_kernel(float* __restrict__ out)
{
    const int ntile = blockIdx.x;  // query tile (64 wide)
    const int ct    = blockIdx.y;  // channel tile (128 tall)
    const int b     = blockIdx.z;
    const size_t ao = ((size_t)b * CDIM + (size_t)ct * 128) * NDIM;
    const size_t bo = ((size_t)b * NDIM + (size_t)ntile * 64) * NDIM;
    float* dst = out + ((size_t)b * CDIM + (size_t)ct * 128) * NDIM + ntile * 64;
    gemm_core(g_Vh + ao, g_Vl + ao, g_Ph + bo, g_Pl + bo, NDIM, NDIM / 32, dst);
}

// ---------------------------------------------------------------------------
// Row softmax over g_S -> normalized P as bf16 hi/lo.
// ---------------------------------------------------------------------------
__global__ __launch_bounds__(256) void softmax_kernel()
{
    __shared__ float red[8];
    const int n = blockIdx.x, b = blockIdx.y;
    const size_t ro = ((size_t)b * NDIM + n) * NDIM;
    const float* row = g_S + ro;
    const int tid = threadIdx.x, lane = tid & 31, wid = tid >> 5;

    float v[16];
    float mx = -INFINITY;
    #pragma unroll
    for (int i = 0; i < 16; i++) {
        v[i] = row[tid + 256 * i];
        mx = fmaxf(mx, v[i]);
    }
    #pragma unroll
    for (int s = 16; s > 0; s >>= 1)
        mx = fmaxf(mx, __shfl_xor_sync(0xffffffffu, mx, s));
    if (lane == 0) red[wid] = mx;
    __syncthreads();
    mx = red[0];
    #pragma unroll
    for (int i = 1; i < 8; i++) mx = fmaxf(mx, red[i]);
    __syncthreads();

    float sum = 0.f;
    #pragma unroll
    for (int i = 0; i < 16; i++) {
        v[i] = __expf(v[i] - mx);
        sum += v[i];
    }
    #pragma unroll
    for (int s = 16; s > 0; s >>= 1)
        sum += __shfl_xor_sync(0xffffffffu, sum, s);
    if (lane == 0) red[wid] = sum;
    __syncthreads();
    sum = red[0];
    #pragma unroll
    for (int i = 1; i < 8; i++) sum += red[i];
    const float inv = 1.f / sum;

    __nv_bfloat16* ph = g_Ph + ro;
    __nv_bfloat16* pl = g_Pl + ro;
    #pragma unroll
    for (int i = 0; i < 16; i++) {
        float p = v[i] * inv;
        __nv_bfloat16 h = __float2bfloat16(p);
        ph[tid + 256 * i] = h;
        pl[tid + 256 * i] = __float2bfloat16(p - __bfloat162float(h));
    }
}

// ---------------------------------------------------------------------------
// Projection: out = W(256x256) @ X(256x4096) + bias; emits bf16 hi/lo splits.
// Q,K stored (B,N,C); V stored (B,C,N).
// ---------------------------------------------------------------------------
union BF4 { __nv_bfloat16 h[4]; uint2 u; };

__global__ __launch_bounds__(256) void proj_kernel(
    const float* __restrict__ x,
    const float* __restrict__ Wq, const float* __restrict__ bq,
    const float* __restrict__ Wk, const float* __restrict__ bk,
    const float* __restrict__ Wv, const float* __restrict__ bv)
{
    __shared__ float w_s[16][68];
    __shared__ float x_s[16][64];

    const int n0 = blockIdx.x * 64;
    const int o0 = blockIdx.y * 64;
    const int b     = blockIdx.z / 3;
    const int which = blockIdx.z % 3;
    const float* W    = (which == 0) ? Wq : (which == 1) ? Wk : Wv;
    const float* bias = (which == 0) ? bq : (which == 1) ? bk : bv;

    const int t  = threadIdx.x;
    const int tx = t & 15;
    const int ty = t >> 4;

    const float* xb = x + (size_t)b * CDIM * NDIM;

    float acc[4][4];
    #pragma unroll
    for (int i = 0; i < 4; i++)
        #pragma unroll
        for (int j = 0; j < 4; j++) acc[i][j] = 0.f;

    const int lo = t >> 2;
    const int lc = (t & 3) << 2;
    const int xr = t >> 4;
    const int xn = (t & 15) << 2;

    for (int c0 = 0; c0 < CDIM; c0 += 16) {
        float4 wv4 = *(const float4*)&W[(size_t)(o0 + lo) * CDIM + c0 + lc];
        float4 xv4 = *(const float4*)&xb[(size_t)(c0 + xr) * NDIM + n0 + xn];
        __syncthreads();
        w_s[lc + 0][lo] = wv4.x;
        w_s[lc + 1][lo] = wv4.y;
        w_s[lc + 2][lo] = wv4.z;
        w_s[lc + 3][lo] = wv4.w;
        *(float4*)&x_s[xr][xn] = xv4;
        __syncthreads();
        #pragma unroll
        for (int kk = 0; kk < 16; kk++) {
            float4 a4 = *(const float4*)&w_s[kk][ty << 2];
            float4 b4 = *(const float4*)&x_s[kk][tx << 2];
            float a[4] = {a4.x, a4.y, a4.z, a4.w};
            float bb[4] = {b4.x, b4.y, b4.z, b4.w};
            #pragma unroll
            for (int i = 0; i < 4; i++)
                #pragma unroll
                for (int j = 0; j < 4; j++)
                    acc[i][j] = fmaf(a[i], bb[j], acc[i][j]);
        }
    }

    float bo[4];
    #pragma unroll
    for (int i = 0; i < 4; i++) bo[i] = bias[o0 + (ty << 2) + i];

    if (which != 2) {
        __nv_bfloat16* dh = (which == 0) ? g_Qh : g_Kh;
        __nv_bfloat16* dl = (which == 0) ? g_Ql : g_Kl;
        #pragma unroll
        for (int j = 0; j < 4; j++) {
            const int n = n0 + (tx << 2) + j;
            BF4 H, L;
            #pragma unroll
            for (int i = 0; i < 4; i++) {
                float v = acc[i][j] + bo[i];
                H.h[i] = __float2bfloat16(v);
                L.h[i] = __float2bfloat16(v - __bfloat162float(H.h[i]));
            }
            const size_t base = ((size_t)b * NDIM + n) * CDIM + o0 + (ty << 2);
            *(uint2*)&dh[base] = H.u;
            *(uint2*)&dl[base] = L.u;
        }
    } else {
        #pragma unroll
        for (int i = 0; i < 4; i++) {
            const int o = o0 + (ty << 2) + i;
            BF4 H, L;
            #pragma unroll
            for (int j = 0; j < 4; j++) {
                float v = acc[i][j] + bo[i];
                H.h[j] = __float2bfloat16(v);
                L.h[j] = __float2bfloat16(v - __bfloat162float(H.h[j]));
            }
            const size_t base = ((size_t)b * CDIM + o) * NDIM + n0 + (tx << 2);
            *(uint2*)&g_Vh[base] = H.u;
            *(uint2*)&g_Vl[base] = L.u;
        }
    }
}

// ---------------------------------------------------------------------------
extern "C" void kernel_launch(void* const* d_in, const int* in_sizes, int n_in,
                              void* d_out, int out_size)
{
    const float* x  = (const float*)d_in[0];
    const float* Wq = (const float*)d_in[1];
    const float* bq = (const float*)d_in[2];
    const float* Wk = (const float*)d_in[3];
    const float* bk = (const float*)d_in[4];
    const float* Wv = (const float*)d_in[5];
    const float* bv = (const float*)d_in[6];
    float* out = (float*)d_out;

    dim3 pg(NDIM / 64, CDIM / 64, BDIM * 3);
    proj_kernel<<<pg, 256>>>(x, Wq, bq, Wk, bk, Wv, bv);

    dim3 qg(NDIM / 64, NDIM / 128, BDIM);
    qk_kernel<<<qg, 256>>>();

    dim3 sg(NDIM, BDIM);
    softmax_kernel<<<sg, 256>>>();

    dim3 vg(NDIM / 64, CDIM / 128, BDIM);
    pv_kernel<<<vg, 256>>>(out);
}

// round 10
// speedup vs baseline: 2.2979x; 1.6759x over previous
#include <cuda_runtime.h>
#include <cuda_bf16.h>
#include <math.h>
#include <stdint.h>

#define BDIM 4
#define CDIM 256
#define NDIM 4096

// ---------------- global scratch (static device allocations) ---------------
__device__ __nv_bfloat16 g_Qh[(size_t)BDIM * NDIM * CDIM];  // (B,N,C)
__device__ __nv_bfloat16 g_Ql[(size_t)BDIM * NDIM * CDIM];
__device__ __nv_bfloat16 g_Kh[(size_t)BDIM * NDIM * CDIM];  // (B,N,C)
__device__ __nv_bfloat16 g_Kl[(size_t)BDIM * NDIM * CDIM];
__device__ __nv_bfloat16 g_Vh[(size_t)BDIM * CDIM * NDIM];  // (B,C,N)
__device__ __nv_bfloat16 g_Vl[(size_t)BDIM * CDIM * NDIM];
__device__ float         g_S [(size_t)BDIM * NDIM * NDIM];  // (B,N,N) energy
__device__ __nv_bfloat16 g_Ph[(size_t)BDIM * NDIM * NDIM];  // (B,N,N) attn hi
__device__ __nv_bfloat16 g_Pl[(size_t)BDIM * NDIM * NDIM];  // (B,N,N) attn lo

// ---------------- PTX helpers (baseline sm_80+ features only) ---------------
__device__ __forceinline__ uint32_t smem_u32(const void* p) {
    uint32_t a;
    asm("{ .reg .u64 t; cvta.to.shared.u64 t, %1; cvt.u32.u64 %0, t; }"
        : "=r"(a) : "l"(p));
    return a;
}
__device__ __forceinline__ void ldsm4(uint32_t* r, uint32_t addr) {
    asm volatile("ldmatrix.sync.aligned.m8n8.x4.shared.b16 {%0,%1,%2,%3}, [%4];"
                 : "=r"(r[0]), "=r"(r[1]), "=r"(r[2]), "=r"(r[3]) : "r"(addr));
}
__device__ __forceinline__ void mma_bf16(float* d, const uint32_t* a,
                                         const uint32_t* b) {
    asm volatile(
        "mma.sync.aligned.m16n8k16.row.col.f32.bf16.bf16.f32 "
        "{%0,%1,%2,%3}, {%4,%5,%6,%7}, {%8,%9}, {%0,%1,%2,%3};"
        : "+f"(d[0]), "+f"(d[1]), "+f"(d[2]), "+f"(d[3])
        : "r"(a[0]), "r"(a[1]), "r"(a[2]), "r"(a[3]), "r"(b[0]), "r"(b[1]));
}
__device__ __forceinline__ void cp16(uint32_t daddr, const void* src) {
    asm volatile("cp.async.ca.shared.global [%0], [%1], 16;"
                 :: "r"(daddr), "l"(src));
}
#define CP_COMMIT() asm volatile("cp.async.commit_group;" ::: "memory")
#define CP_WAIT1()  asm volatile("cp.async.wait_group 1;" ::: "memory")
#define CP_WAIT0()  asm volatile("cp.async.wait_group 0;" ::: "memory")

// ---------------------------------------------------------------------------
// Split-bf16 warp-MMA GEMM core, v2.
//   D(128x128 fp32) = sum_k A[128,K] * B[128,K]^T,  A,B as bf16 (hi,lo),
//   D += Ah*Bh + Ah*Bl + Al*Bh  (Al*Bl dropped, ~2^-18 error).
// K in chunks of 32. cp.async double-buffered SMEM (2 x 40KB), 80B row pad
// (conflict-free ldmatrix). 8 warps = 4(m) x 2(n); warp tile 32x64;
// 64 fp32 acc/thread.  SMEM rows: [0,128) Ah [128,256) Al [256,384) Bh
// [384,512) Bl; row stride SROW bytes, 64 data bytes (32 bf16) per row.
// ---------------------------------------------------------------------------
#define SROW      80
#define BUF_BYTES (512 * SROW)          // 40960
#define GEMM_SMEM (2 * BUF_BYTES)       // 81920

__device__ __forceinline__ void gemm_core(
    const __nv_bfloat16* __restrict__ Ah, const __nv_bfloat16* __restrict__ Al,
    const __nv_bfloat16* __restrict__ Bh, const __nv_bfloat16* __restrict__ Bl,
    int kstride, int nchunks, float* __restrict__ dst)
{
    extern __shared__ __align__(16) char smem[];
    const uint32_t sb = smem_u32(smem);
    const int tid  = threadIdx.x;
    const int lane = tid & 31;
    const int wid  = tid >> 5;
    const int m0   = (wid & 3) * 32;
    const int n0   = (wid >> 2) * 64;

    // ---- staging map: 8 x 16B cp.async per thread per chunk ---------------
    const __nv_bfloat16* src[8];
    uint32_t dof[8];
    #pragma unroll
    for (int i = 0; i < 8; i++) {
        int u = i * 256 + tid;
        int row = u >> 2, c16 = u & 3;
        const __nv_bfloat16* base;
        int r;
        if (row < 128)      { base = Ah; r = row; }
        else if (row < 256) { base = Al; r = row - 128; }
        else if (row < 384) { base = Bh; r = row - 256; }
        else                { base = Bl; r = row - 384; }
        src[i] = base + (size_t)r * kstride + c16 * 8;
        dof[i] = sb + (uint32_t)row * SROW + c16 * 16;
    }

    // ---- ldmatrix lane addressing -----------------------------------------
    const int g = lane >> 3, r8 = lane & 7;
    const int rowA = (g & 1) * 8 + r8, kkA = (g >> 1) * 8;  // a0,a1,a2,a3
    const int rowB = (g >> 1) * 8 + r8, kkB = (g & 1) * 8;  // b pairs
    uint32_t aAh[2], aAl[2], aBh[4], aBl[4];
    #pragma unroll
    for (int mt = 0; mt < 2; mt++) {
        aAh[mt] = sb + (uint32_t)(0   + m0 + mt * 16 + rowA) * SROW + kkA * 2;
        aAl[mt] = sb + (uint32_t)(128 + m0 + mt * 16 + rowA) * SROW + kkA * 2;
    }
    #pragma unroll
    for (int np = 0; np < 4; np++) {
        aBh[np] = sb + (uint32_t)(256 + n0 + np * 16 + rowB) * SROW + kkB * 2;
        aBl[np] = sb + (uint32_t)(384 + n0 + np * 16 + rowB) * SROW + kkB * 2;
    }

    float acc[2][8][4];
    #pragma unroll
    for (int mt = 0; mt < 2; mt++)
        #pragma unroll
        for (int nt = 0; nt < 8; nt++)
            #pragma unroll
            for (int e = 0; e < 4; e++) acc[mt][nt][e] = 0.f;

    // prologue: stage chunk 0 into buffer 0
    #pragma unroll
    for (int i = 0; i < 8; i++) cp16(dof[i], src[i]);
    CP_COMMIT();

    for (int ci = 0; ci < nchunks; ci++) {
        const uint32_t bofs = (ci & 1) ? BUF_BYTES : 0;
        if (ci + 1 < nchunks) {
            const uint32_t nofs = (ci & 1) ? 0 : BUF_BYTES;
            const int co = (ci + 1) * 32;
            #pragma unroll
            for (int i = 0; i < 8; i++) cp16(dof[i] + nofs, src[i] + co);
            CP_COMMIT();
            CP_WAIT1();
        } else {
            CP_WAIT0();
        }
        __syncthreads();

        #pragma unroll
        for (int k16 = 0; k16 < 2; k16++) {
            const uint32_t kb = bofs + k16 * 32;
            uint32_t ah[2][4], al[2][4], bh[4][4], bl[4][4];
            #pragma unroll
            for (int mt = 0; mt < 2; mt++) {
                ldsm4(ah[mt], aAh[mt] + kb);
                ldsm4(al[mt], aAl[mt] + kb);
            }
            #pragma unroll
            for (int np = 0; np < 4; np++) {
                ldsm4(bh[np], aBh[np] + kb);
                ldsm4(bl[np], aBl[np] + kb);
            }
            #pragma unroll
            for (int mt = 0; mt < 2; mt++)
                #pragma unroll
                for (int nt = 0; nt < 8; nt++) {
                    const uint32_t* bfh = &bh[nt >> 1][(nt & 1) * 2];
                    const uint32_t* bfl = &bl[nt >> 1][(nt & 1) * 2];
                    mma_bf16(acc[mt][nt], ah[mt], bfh);
                    mma_bf16(acc[mt][nt], ah[mt], bfl);
                    mma_bf16(acc[mt][nt], al[mt], bfh);
                }
        }
        __syncthreads();   // compute done before this buffer is restaged
    }

    // ---- epilogue: fragment row = lane>>2 (+8), col = 2*(lane&3) ----------
    const int er = lane >> 2, ec = (lane & 3) * 2;
    #pragma unroll
    for (int mt = 0; mt < 2; mt++)
        #pragma unroll
        for (int nt = 0; nt < 8; nt++) {
            const int rr = m0 + mt * 16 + er;
            const int cc = n0 + nt * 8 + ec;
            *(float2*)&dst[(size_t)rr * NDIM + cc] =
                make_float2(acc[mt][nt][0], acc[mt][nt][1]);
            *(float2*)&dst[(size_t)(rr + 8) * NDIM + cc] =
                make_float2(acc[mt][nt][2], acc[mt][nt][3]);
        }
}

// ---------------------------------------------------------------------------
// QK: S[b, n, m] = sum_c q[b,n,c] * k[b,m,c].  A=Q rows n, B=K rows m.
// ---------------------------------------------------------------------------
__global__ __launch_bounds__(256, 1) void qk_kernel()
{
    const int mt = blockIdx.x;   // key tile (128)
    const int nt = blockIdx.y;   // query tile (128)
    const int b  = blockIdx.z;
    const size_t ao = ((size_t)b * NDIM + (size_t)nt * 128) * CDIM;
    const size_t bo = ((size_t)b * NDIM + (size_t)mt * 128) * CDIM;
    float* dst = g_S + ((size_t)b * NDIM + (size_t)nt * 128) * NDIM + mt * 128;
    gemm_core(g_Qh + ao, g_Ql + ao, g_Kh + bo, g_Kl + bo, CDIM, CDIM / 32, dst);
}

// ---------------------------------------------------------------------------
// PV: out[b, c, n] = sum_m v[b,c,m] * P[b,n,m].  A=V rows c, B=P rows n.
// ---------------------------------------------------------------------------
__global__ __launch_bounds__(256, 1) void pv_kernel(float* __restrict__ out)
{
    const int ntile = blockIdx.x;  // query tile (128)
    const int ct    = blockIdx.y;  // channel tile (128)
    const int b     = blockIdx.z;
    const size_t ao = ((size_t)b * CDIM + (size_t)ct * 128) * NDIM;
    const size_t bo = ((size_t)b * NDIM + (size_t)ntile * 128) * NDIM;
    float* dst = out + ((size_t)b * CDIM + (size_t)ct * 128) * NDIM + ntile * 128;
    gemm_core(g_Vh + ao, g_Vl + ao, g_Ph + bo, g_Pl + bo, NDIM, NDIM / 32, dst);
}

// ---------------------------------------------------------------------------
// Row softmax over g_S -> normalized P as bf16 hi/lo. float4 I/O.
// ---------------------------------------------------------------------------
union BF4 { __nv_bfloat16 h[4]; uint2 u; };

__global__ __launch_bounds__(256) void softmax_kernel()
{
    __shared__ float red[8];
    const int n = blockIdx.x, b = blockIdx.y;
    const size_t ro = ((size_t)b * NDIM + n) * NDIM;
    const int tid = threadIdx.x, lane = tid & 31, wid = tid >> 5;

    const float4* row4 = (const float4*)(g_S + ro);
    float4 v[4];
    float mx = -INFINITY;
    #pragma unroll
    for (int i = 0; i < 4; i++) {
        v[i] = row4[i * 256 + tid];
        mx = fmaxf(mx, fmaxf(fmaxf(v[i].x, v[i].y), fmaxf(v[i].z, v[i].w)));
    }
    #pragma unroll
    for (int s = 16; s > 0; s >>= 1)
        mx = fmaxf(mx, __shfl_xor_sync(0xffffffffu, mx, s));
    if (lane == 0) red[wid] = mx;
    __syncthreads();
    mx = red[0];
    #pragma unroll
    for (int i = 1; i < 8; i++) mx = fmaxf(mx, red[i]);
    __syncthreads();

    float sum = 0.f;
    #pragma unroll
    for (int i = 0; i < 4; i++) {
        v[i].x = __expf(v[i].x - mx); sum += v[i].x;
        v[i].y = __expf(v[i].y - mx); sum += v[i].y;
        v[i].z = __expf(v[i].z - mx); sum += v[i].z;
        v[i].w = __expf(v[i].w - mx); sum += v[i].w;
    }
    #pragma unroll
    for (int s = 16; s > 0; s >>= 1)
        sum += __shfl_xor_sync(0xffffffffu, sum, s);
    if (lane == 0) red[wid] = sum;
    __syncthreads();
    sum = red[0];
    #pragma unroll
    for (int i = 1; i < 8; i++) sum += red[i];
    const float inv = 1.f / sum;

    uint2* ph2 = (uint2*)(g_Ph + ro);
    uint2* pl2 = (uint2*)(g_Pl + ro);
    #pragma unroll
    for (int i = 0; i < 4; i++) {
        float p0 = v[i].x * inv, p1 = v[i].y * inv;
        float p2 = v[i].z * inv, p3 = v[i].w * inv;
        BF4 H, L;
        H.h[0] = __float2bfloat16(p0);
        H.h[1] = __float2bfloat16(p1);
        H.h[2] = __float2bfloat16(p2);
        H.h[3] = __float2bfloat16(p3);
        L.h[0] = __float2bfloat16(p0 - __bfloat162float(H.h[0]));
        L.h[1] = __float2bfloat16(p1 - __bfloat162float(H.h[1]));
        L.h[2] = __float2bfloat16(p2 - __bfloat162float(H.h[2]));
        L.h[3] = __float2bfloat16(p3 - __bfloat162float(H.h[3]));
        ph2[i * 256 + tid] = H.u;
        pl2[i * 256 + tid] = L.u;
    }
}

// ---------------------------------------------------------------------------
// Projection: out = W(256x256) @ X(256x4096) + bias; emits bf16 hi/lo splits.
// Q,K stored (B,N,C); V stored (B,C,N).
// ---------------------------------------------------------------------------
__global__ __launch_bounds__(256) void proj_kernel(
    const float* __restrict__ x,
    const float* __restrict__ Wq, const float* __restrict__ bq,
    const float* __restrict__ Wk, const float* __restrict__ bk,
    const float* __restrict__ Wv, const float* __restrict__ bv)
{
    __shared__ float w_s[16][68];
    __shared__ float x_s[16][64];

    const int n0 = blockIdx.x * 64;
    const int o0 = blockIdx.y * 64;
    const int b     = blockIdx.z / 3;
    const int which = blockIdx.z % 3;
    const float* W    = (which == 0) ? Wq : (which == 1) ? Wk : Wv;
    const float* bias = (which == 0) ? bq : (which == 1) ? bk : bv;

    const int t  = threadIdx.x;
    const int tx = t & 15;
    const int ty = t >> 4;

    const float* xb = x + (size_t)b * CDIM * NDIM;

    float acc[4][4];
    #pragma unroll
    for (int i = 0; i < 4; i++)
        #pragma unroll
        for (int j = 0; j < 4; j++) acc[i][j] = 0.f;

    const int lo = t >> 2;
    const int lc = (t & 3) << 2;
    const int xr = t >> 4;
    const int xn = (t & 15) << 2;

    for (int c0 = 0; c0 < CDIM; c0 += 16) {
        float4 wv4 = *(const float4*)&W[(size_t)(o0 + lo) * CDIM + c0 + lc];
        float4 xv4 = *(const float4*)&xb[(size_t)(c0 + xr) * NDIM + n0 + xn];
        __syncthreads();
        w_s[lc + 0][lo] = wv4.x;
        w_s[lc + 1][lo] = wv4.y;
        w_s[lc + 2][lo] = wv4.z;
        w_s[lc + 3][lo] = wv4.w;
        *(float4*)&x_s[xr][xn] = xv4;
        __syncthreads();
        #pragma unroll
        for (int kk = 0; kk < 16; kk++) {
            float4 a4 = *(const float4*)&w_s[kk][ty << 2];
            float4 b4 = *(const float4*)&x_s[kk][tx << 2];
            float a[4] = {a4.x, a4.y, a4.z, a4.w};
            float bb[4] = {b4.x, b4.y, b4.z, b4.w};
            #pragma unroll
            for (int i = 0; i < 4; i++)
                #pragma unroll
                for (int j = 0; j < 4; j++)
                    acc[i][j] = fmaf(a[i], bb[j], acc[i][j]);
        }
    }

    float bo[4];
    #pragma unroll
    for (int i = 0; i < 4; i++) bo[i] = bias[o0 + (ty << 2) + i];

    if (which != 2) {
        __nv_bfloat16* dh = (which == 0) ? g_Qh : g_Kh;
        __nv_bfloat16* dl = (which == 0) ? g_Ql : g_Kl;
        #pragma unroll
        for (int j = 0; j < 4; j++) {
            const int n = n0 + (tx << 2) + j;
            BF4 H, L;
            #pragma unroll
            for (int i = 0; i < 4; i++) {
                float v = acc[i][j] + bo[i];
                H.h[i] = __float2bfloat16(v);
                L.h[i] = __float2bfloat16(v - __bfloat162float(H.h[i]));
            }
            const size_t base = ((size_t)b * NDIM + n) * CDIM + o0 + (ty << 2);
            *(uint2*)&dh[base] = H.u;
            *(uint2*)&dl[base] = L.u;
        }
    } else {
        #pragma unroll
        for (int i = 0; i < 4; i++) {
            const int o = o0 + (ty << 2) + i;
            BF4 H, L;
            #pragma unroll
            for (int j = 0; j < 4; j++) {
                float v = acc[i][j] + bo[i];
                H.h[j] = __float2bfloat16(v);
                L.h[j] = __float2bfloat16(v - __bfloat162float(H.h[j]));
            }
            const size_t base = ((size_t)b * CDIM + o) * NDIM + n0 + (tx << 2);
            *(uint2*)&g_Vh[base] = H.u;
            *(uint2*)&g_Vl[base] = L.u;
        }
    }
}

// ---------------------------------------------------------------------------
extern "C" void kernel_launch(void* const* d_in, const int* in_sizes, int n_in,
                              void* d_out, int out_size)
{
    const float* x  = (const float*)d_in[0];
    const float* Wq = (const float*)d_in[1];
    const float* bq = (const float*)d_in[2];
    const float* Wk = (const float*)d_in[3];
    const float* bk = (const float*)d_in[4];
    const float* Wv = (const float*)d_in[5];
    const float* bv = (const float*)d_in[6];
    float* out = (float*)d_out;

    cudaFuncSetAttribute(qk_kernel,
                         cudaFuncAttributeMaxDynamicSharedMemorySize, GEMM_SMEM);
    cudaFuncSetAttribute(pv_kernel,
                         cudaFuncAttributeMaxDynamicSharedMemorySize, GEMM_SMEM);

    dim3 pg(NDIM / 64, CDIM / 64, BDIM * 3);
    proj_kernel<<<pg, 256>>>(x, Wq, bq, Wk, bk, Wv, bv);

    dim3 qg(NDIM / 128, NDIM / 128, BDIM);
    qk_kernel<<<qg, 256, GEMM_SMEM>>>();

    dim3 sg(NDIM, BDIM);
    softmax_kernel<<<sg, 256>>>();

    dim3 vg(NDIM / 128, CDIM / 128, BDIM);
    pv_kernel<<<vg, 256, GEMM_SMEM>>>(out);
}